// round 5
// baseline (speedup 1.0000x reference)
#include <cuda_runtime.h>
#include <cstdint>

// Problem constants
#define NM 100000
#define NT 100000
#define NE 400000
#define DD 128
#define K2 256   // concat K dim: [agg | x_dst]
#define NMAX 100000   // max(NM, NT)

#define CDIV(a,b) (((a)+(b)-1)/(b))

// ---------------- scratch (static __device__ allocations, 16B-aligned) ----
__device__ float4 g_agg_t[(size_t)NT * DD / 4];
__device__ float4 g_agg_m[(size_t)NM * DD / 4];
__device__ float4 g_bm0[(size_t)NM * DD / 4];
__device__ float4 g_bm1[(size_t)NM * DD / 4];
__device__ float4 g_bt0[(size_t)NT * DD / 4];
__device__ float4 g_bt1[(size_t)NT * DD / 4];
__device__ float4 g_Bext[3 * 2 * K2 * DD / 4];   // [layer][type][k][j]
__device__ int    g_e32_mt[2 * NE];
__device__ int    g_e32_tm[2 * NE];
__device__ int    g_is32;
// CSR scratch (x2 edge types)
__device__ int    g_cnt_t[NT];
__device__ int    g_cnt_m[NM];
__device__ int    g_off_t[NT + 1];
__device__ int    g_off_m[NM + 1];
__device__ int    g_cur_t[NT];
__device__ int    g_cur_m[NM];
__device__ int    g_csr_t[NE];     // src ids sorted by dst (tracks as dst)
__device__ int    g_csr_m[NE];     // src ids sorted by dst (musicians as dst)

// ---------------- edge dtype detect + convert ----------------
__global__ void detect_reset() { g_is32 = 0; }

__global__ void detect_kernel(const unsigned* __restrict__ p) {
    int i = blockIdx.x * blockDim.x + threadIdx.x;
    unsigned v = 0;
    for (int w = i * 2 + 1; w < 2 * NE; w += gridDim.x * blockDim.x * 2)
        v |= p[w];
    if (__syncthreads_or(v != 0) && threadIdx.x == 0) atomicExch(&g_is32, 1);
}

__global__ void convert_kernel(const void* __restrict__ e, int* __restrict__ out) {
    int i = blockIdx.x * blockDim.x + threadIdx.x;
    if (i >= 2 * NE) return;
    int v;
    if (g_is32) v = ((const int*)e)[i];
    else        v = (int)((const long long*)e)[i];
    out[i] = min(max(v, 0), NMAX - 1);
}

// ---------------- CSR build ----------------
__global__ void zero_int(int* p, int n) {
    int i = blockIdx.x * blockDim.x + threadIdx.x;
    if (i < n) p[i] = 0;
}

__global__ void hist_kernel(const int* __restrict__ edge, int* __restrict__ cnt) {
    int i = blockIdx.x * blockDim.x + threadIdx.x;
    if (i < NE) atomicAdd(&cnt[edge[NE + i]], 1);
}

// single-block exclusive scan over n ints (n <= 1024 * CHUNK)
__global__ void scan_kernel(const int* __restrict__ cnt, int* __restrict__ off,
                            int* __restrict__ cur, int n) {
    __shared__ int partial[1024];
    const int tid = threadIdx.x;
    const int per = CDIV(n, 1024);
    const int base = tid * per;
    int sum = 0;
    for (int i = 0; i < per; i++) {
        int idx = base + i;
        if (idx < n) sum += cnt[idx];
    }
    partial[tid] = sum;
    __syncthreads();
    // Hillis-Steele inclusive scan
    for (int d = 1; d < 1024; d <<= 1) {
        int t = (tid >= d) ? partial[tid - d] : 0;
        __syncthreads();
        partial[tid] += t;
        __syncthreads();
    }
    int run = partial[tid] - sum;   // exclusive prefix of this chunk
    for (int i = 0; i < per; i++) {
        int idx = base + i;
        if (idx < n) { off[idx] = run; cur[idx] = run; run += cnt[idx]; }
    }
    if (tid == 1023) off[n] = partial[1023];
}

__global__ void fill_kernel(const int* __restrict__ edge, int* __restrict__ cur,
                            int* __restrict__ csr) {
    int i = blockIdx.x * blockDim.x + threadIdx.x;
    if (i >= NE) return;
    int src = edge[i];
    int dst = edge[NE + i];
    int pos = atomicAdd(&cur[dst], 1);
    csr[pos] = src;
}

// ---------------- CSR mean-aggregation: warp per dst row ----------------
__global__ void aggregate_csr(const float* __restrict__ xsrc,
                              const int* __restrict__ csr,
                              const int* __restrict__ off,
                              float* __restrict__ agg, int n) {
    int w = (blockIdx.x * blockDim.x + threadIdx.x) >> 5;
    int lane = threadIdx.x & 31;
    if (w >= n) return;
    int s = off[w], e = off[w + 1];
    float4 acc = make_float4(0.f, 0.f, 0.f, 0.f);
    for (int i = s; i < e; i++) {
        int src = csr[i];
        float4 v = ((const float4*)(xsrc + (size_t)src * DD))[lane];
        acc.x += v.x; acc.y += v.y; acc.z += v.z; acc.w += v.w;
    }
    float inv = 1.0f / fmaxf((float)(e - s), 1.0f);
    ((float4*)(agg + (size_t)w * DD))[lane] =
        make_float4(acc.x * inv, acc.y * inv, acc.z * inv, acc.w * inv);
}

// ---------------- small utility kernels ----------------
// Build B_ext[lt][k][j] = (k < D ? Wl[lt][j][k] : Wr[lt][j][k-D])
__global__ void prep_weights(const float* __restrict__ Wl,
                             const float* __restrict__ Wr,
                             float* __restrict__ Bext) {
    int i = blockIdx.x * blockDim.x + threadIdx.x;
    if (i >= 3 * 2 * K2 * DD) return;
    int j  = i % DD;
    int k  = (i / DD) % K2;
    int lt = i / (DD * K2);
    float v = (k < DD) ? Wl[((size_t)lt * DD + j) * DD + k]
                       : Wr[((size_t)lt * DD + j) * DD + (k - DD)];
    Bext[i] = v;
}

// ---------------- tf32 tensor-core fused SAGE GEMM ----------------
// C[i,j] = sum_{k<128} agg[i,k]*B[k,j] + sum_k x[i,k]*B[128+k,j] + bias[j]
__device__ __forceinline__ uint32_t f2tf32(float f) {
    uint32_t r;
    asm("cvt.rna.tf32.f32 %0, %1;" : "=r"(r) : "f"(f));
    return r;
}

__global__ void __launch_bounds__(256)
gemm_sage_tc(const float* __restrict__ Aagg,
             const float* __restrict__ Xdst, const float* __restrict__ B,
             const float* __restrict__ bias, float* __restrict__ Cout,
             int nRows, int relu) {
    __shared__ uint32_t As[128][36];
    __shared__ uint32_t Bs[32][136];

    const int tid  = threadIdx.x;
    const int wid  = tid >> 5;
    const int lane = tid & 31;
    const int g    = lane >> 2;
    const int t    = lane & 3;
    const int m0   = (wid & 1) * 64;
    const int n0   = (wid >> 1) * 32;
    const int rowBase = blockIdx.x * 128;

    float acc[4][4][4];
#pragma unroll
    for (int im = 0; im < 4; im++)
#pragma unroll
        for (int in = 0; in < 4; in++)
#pragma unroll
            for (int q = 0; q < 4; q++) acc[im][in][q] = 0.f;

    for (int kt = 0; kt < K2; kt += 32) {
#pragma unroll
        for (int p = 0; p < 4; p++) {
            int f = tid + p * 256;
            int r = f >> 3;
            int q = f & 7;
            int gr = rowBase + r;
            if (gr >= nRows) gr = nRows - 1;
            int kg = kt + q * 4;
            const float* src = (kg < DD) ? (Aagg + (size_t)gr * DD + kg)
                                         : (Xdst + (size_t)gr * DD + (kg - DD));
            float4 v = *(const float4*)src;
            As[r][q * 4 + 0] = f2tf32(v.x);
            As[r][q * 4 + 1] = f2tf32(v.y);
            As[r][q * 4 + 2] = f2tf32(v.z);
            As[r][q * 4 + 3] = f2tf32(v.w);
        }
#pragma unroll
        for (int p = 0; p < 4; p++) {
            int f = tid + p * 256;
            int kr = f >> 5;
            int c  = f & 31;
            float4 v = *(const float4*)(B + (size_t)(kt + kr) * DD + c * 4);
            Bs[kr][c * 4 + 0] = f2tf32(v.x);
            Bs[kr][c * 4 + 1] = f2tf32(v.y);
            Bs[kr][c * 4 + 2] = f2tf32(v.z);
            Bs[kr][c * 4 + 3] = f2tf32(v.w);
        }
        __syncthreads();

#pragma unroll
        for (int kk = 0; kk < 32; kk += 8) {
            uint32_t a[4][4], b[4][2];
#pragma unroll
            for (int im = 0; im < 4; im++) {
                int rm = m0 + im * 16 + g;
                a[im][0] = As[rm][kk + t];
                a[im][1] = As[rm + 8][kk + t];
                a[im][2] = As[rm][kk + t + 4];
                a[im][3] = As[rm + 8][kk + t + 4];
            }
#pragma unroll
            for (int in = 0; in < 4; in++) {
                int cn = n0 + in * 8 + g;
                b[in][0] = Bs[kk + t][cn];
                b[in][1] = Bs[kk + t + 4][cn];
            }
#pragma unroll
            for (int im = 0; im < 4; im++)
#pragma unroll
                for (int in = 0; in < 4; in++) {
                    asm volatile(
                        "mma.sync.aligned.m16n8k8.row.col.f32.tf32.tf32.f32 "
                        "{%0,%1,%2,%3}, {%4,%5,%6,%7}, {%8,%9}, {%0,%1,%2,%3};"
                        : "+f"(acc[im][in][0]), "+f"(acc[im][in][1]),
                          "+f"(acc[im][in][2]), "+f"(acc[im][in][3])
                        : "r"(a[im][0]), "r"(a[im][1]), "r"(a[im][2]), "r"(a[im][3]),
                          "r"(b[in][0]), "r"(b[in][1]));
                }
        }
        __syncthreads();
    }

#pragma unroll
    for (int in = 0; in < 4; in++) {
        int col = n0 + in * 8 + 2 * t;
        float b0 = bias[col], b1 = bias[col + 1];
#pragma unroll
        for (int im = 0; im < 4; im++) {
            int r0 = rowBase + m0 + im * 16 + g;
            float v0 = acc[im][in][0] + b0;
            float v1 = acc[im][in][1] + b1;
            float v2 = acc[im][in][2] + b0;
            float v3 = acc[im][in][3] + b1;
            if (relu) {
                v0 = fmaxf(v0, 0.f); v1 = fmaxf(v1, 0.f);
                v2 = fmaxf(v2, 0.f); v3 = fmaxf(v3, 0.f);
            }
            if (r0 < nRows)
                *(float2*)(Cout + (size_t)r0 * DD + col) = make_float2(v0, v1);
            if (r0 + 8 < nRows)
                *(float2*)(Cout + (size_t)(r0 + 8) * DD + col) = make_float2(v2, v3);
        }
    }
}

// ---------------- launch ----------------
extern "C" void kernel_launch(void* const* d_in, const int* in_sizes, int n_in,
                              void* d_out, int out_size) {
    const float* x_m = (const float*)d_in[0];
    const float* x_t = (const float*)d_in[1];
    const float* Wl  = (const float*)d_in[2];
    const float* bl  = (const float*)d_in[3];
    const float* Wr  = (const float*)d_in[4];
    const void*  e_mt = d_in[5];
    const void*  e_tm = d_in[6];
    float* out = (float*)d_out;

    float *agg_t, *agg_m, *bm0, *bm1, *bt0, *bt1, *Bext;
    int *e32_mt, *e32_tm, *cnt_t, *cnt_m, *off_t, *off_m, *cur_t, *cur_m, *csr_t, *csr_m;
    cudaGetSymbolAddress((void**)&agg_t, g_agg_t);
    cudaGetSymbolAddress((void**)&agg_m, g_agg_m);
    cudaGetSymbolAddress((void**)&bm0, g_bm0);
    cudaGetSymbolAddress((void**)&bm1, g_bm1);
    cudaGetSymbolAddress((void**)&bt0, g_bt0);
    cudaGetSymbolAddress((void**)&bt1, g_bt1);
    cudaGetSymbolAddress((void**)&Bext, g_Bext);
    cudaGetSymbolAddress((void**)&e32_mt, g_e32_mt);
    cudaGetSymbolAddress((void**)&e32_tm, g_e32_tm);
    cudaGetSymbolAddress((void**)&cnt_t, g_cnt_t);
    cudaGetSymbolAddress((void**)&cnt_m, g_cnt_m);
    cudaGetSymbolAddress((void**)&off_t, g_off_t);
    cudaGetSymbolAddress((void**)&off_m, g_off_m);
    cudaGetSymbolAddress((void**)&cur_t, g_cur_t);
    cudaGetSymbolAddress((void**)&cur_m, g_cur_m);
    cudaGetSymbolAddress((void**)&csr_t, g_csr_t);
    cudaGetSymbolAddress((void**)&csr_m, g_csr_m);

    // ---- edge dtype detection + conversion to int32 ----
    detect_reset<<<1, 1>>>();
    detect_kernel<<<256, 256>>>((const unsigned*)e_mt);
    convert_kernel<<<CDIV(2 * NE, 256), 256>>>(e_mt, e32_mt);
    convert_kernel<<<CDIV(2 * NE, 256), 256>>>(e_tm, e32_tm);

    // ---- CSR build (once; reused by all 3 layers) ----
    zero_int<<<CDIV(NT, 256), 256>>>(cnt_t, NT);
    zero_int<<<CDIV(NM, 256), 256>>>(cnt_m, NM);
    hist_kernel<<<CDIV(NE, 256), 256>>>(e32_mt, cnt_t);
    hist_kernel<<<CDIV(NE, 256), 256>>>(e32_tm, cnt_m);
    scan_kernel<<<1, 1024>>>(cnt_t, off_t, cur_t, NT);
    scan_kernel<<<1, 1024>>>(cnt_m, off_m, cur_m, NM);
    fill_kernel<<<CDIV(NE, 256), 256>>>(e32_mt, cur_t, csr_t);
    fill_kernel<<<CDIV(NE, 256), 256>>>(e32_tm, cur_m, csr_m);

    // weight transpose/concat
    prep_weights<<<CDIV(3 * 2 * K2 * DD, 256), 256>>>(Wl, Wr, Bext);

    const float* xm_cur = x_m;
    const float* xt_cur = x_t;
    float* out_m = out;
    float* out_t = out + (size_t)NM * DD;

    const int aggBlocksT = CDIV(NT * 32, 256);
    const int aggBlocksM = CDIV(NM * 32, 256);

    for (int layer = 0; layer < 3; layer++) {
        float* xt_next = (layer == 2) ? out_t : ((layer == 0) ? bt0 : bt1);
        float* xm_next = (layer == 2) ? out_m : ((layer == 0) ? bm0 : bm1);
        int relu = (layer < 2) ? 1 : 0;

        // mean aggregation via CSR (pre-scaled by 1/deg)
        aggregate_csr<<<aggBlocksT, 256>>>(xm_cur, csr_t, off_t, agg_t, NT);
        aggregate_csr<<<aggBlocksM, 256>>>(xt_cur, csr_m, off_m, agg_m, NM);

        gemm_sage_tc<<<CDIV(NT, 128), 256>>>(
            agg_t, xt_cur,
            Bext + (size_t)(layer * 2 + 0) * K2 * DD,
            bl + (size_t)(layer * 2 + 0) * DD,
            xt_next, NT, relu);
        gemm_sage_tc<<<CDIV(NM, 128), 256>>>(
            agg_m, xm_cur,
            Bext + (size_t)(layer * 2 + 1) * K2 * DD,
            bl + (size_t)(layer * 2 + 1) * DD,
            xm_next, NM, relu);

        xm_cur = xm_next;
        xt_cur = xt_next;
    }
}

// round 6
// speedup vs baseline: 1.4299x; 1.4299x over previous
#include <cuda_runtime.h>
#include <cstdint>

// Problem constants
#define NM 100000
#define NT 100000
#define NE 400000
#define DD 128
#define K2 256   // concat K dim: [agg | x_dst]
#define NMAX 100000   // max(NM, NT)

#define CDIV(a,b) (((a)+(b)-1)/(b))

// ---------------- scratch (static __device__ allocations, 16B-aligned) ----
__device__ float4 g_agg_t[(size_t)NT * DD / 4];
__device__ float4 g_agg_m[(size_t)NM * DD / 4];
__device__ float4 g_bm0[(size_t)NM * DD / 4];
__device__ float4 g_bm1[(size_t)NM * DD / 4];
__device__ float4 g_bt0[(size_t)NT * DD / 4];
__device__ float4 g_bt1[(size_t)NT * DD / 4];
__device__ float4 g_Bext[3 * 2 * K2 * DD / 4];   // [layer][type][k][j]
__device__ int    g_e32_mt[2 * NE];
__device__ int    g_e32_tm[2 * NE];
__device__ int    g_is32;
// CSR scratch (x2 edge types)
__device__ int    g_cnt_t[NT];
__device__ int    g_cnt_m[NM];
__device__ int    g_off_t[NT + 1];
__device__ int    g_off_m[NM + 1];
__device__ int    g_cur_t[NT];
__device__ int    g_cur_m[NM];
__device__ int    g_csr_t[NE];     // src ids sorted by dst (tracks as dst)
__device__ int    g_csr_m[NE];     // src ids sorted by dst (musicians as dst)

// ---------------- edge dtype detect + convert ----------------
__global__ void detect_reset() { g_is32 = 0; }

__global__ void detect_kernel(const unsigned* __restrict__ p) {
    int i = blockIdx.x * blockDim.x + threadIdx.x;
    unsigned v = 0;
    for (int w = i * 2 + 1; w < 2 * NE; w += gridDim.x * blockDim.x * 2)
        v |= p[w];
    if (__syncthreads_or(v != 0) && threadIdx.x == 0) atomicExch(&g_is32, 1);
}

__global__ void convert_kernel(const void* __restrict__ e, int* __restrict__ out) {
    int i = blockIdx.x * blockDim.x + threadIdx.x;
    if (i >= 2 * NE) return;
    int v;
    if (g_is32) v = ((const int*)e)[i];
    else        v = (int)((const long long*)e)[i];
    out[i] = min(max(v, 0), NMAX - 1);
}

// ---------------- CSR build ----------------
__global__ void zero_int(int* p, int n) {
    int i = blockIdx.x * blockDim.x + threadIdx.x;
    if (i < n) p[i] = 0;
}

__global__ void hist_kernel(const int* __restrict__ edge, int* __restrict__ cnt) {
    int i = blockIdx.x * blockDim.x + threadIdx.x;
    if (i < NE) atomicAdd(&cnt[edge[NE + i]], 1);
}

// single-block exclusive scan over n ints
__global__ void scan_kernel(const int* __restrict__ cnt, int* __restrict__ off,
                            int* __restrict__ cur, int n) {
    __shared__ int partial[1024];
    const int tid = threadIdx.x;
    const int per = CDIV(n, 1024);
    const int base = tid * per;
    int sum = 0;
    for (int i = 0; i < per; i++) {
        int idx = base + i;
        if (idx < n) sum += cnt[idx];
    }
    partial[tid] = sum;
    __syncthreads();
    for (int d = 1; d < 1024; d <<= 1) {
        int t = (tid >= d) ? partial[tid - d] : 0;
        __syncthreads();
        partial[tid] += t;
        __syncthreads();
    }
    int run = partial[tid] - sum;
    for (int i = 0; i < per; i++) {
        int idx = base + i;
        if (idx < n) { off[idx] = run; cur[idx] = run; run += cnt[idx]; }
    }
    if (tid == 1023) off[n] = partial[1023];
}

__global__ void fill_kernel(const int* __restrict__ edge, int* __restrict__ cur,
                            int* __restrict__ csr) {
    int i = blockIdx.x * blockDim.x + threadIdx.x;
    if (i >= NE) return;
    int src = edge[i];
    int dst = edge[NE + i];
    int pos = atomicAdd(&cur[dst], 1);
    csr[pos] = src;
}

// ---------------- CSR mean-aggregation: warp per dst, MLP-batched ----------
// Fix for R5 regression: prefetch neighbor ids via lanes + shfl, then issue
// 8 INDEPENDENT row loads back-to-back (OOB lanes clamp to row 0, masked by
// FMA weight 0) so the warp has MLP=8 instead of a serial dependent chain.
__global__ void __launch_bounds__(256)
aggregate_csr(const float* __restrict__ xsrc,
              const int* __restrict__ csr,
              const int* __restrict__ off,
              float* __restrict__ agg, int n) {
    int w = (blockIdx.x * blockDim.x + threadIdx.x) >> 5;
    int lane = threadIdx.x & 31;
    if (w >= n) return;
    int s = off[w], e = off[w + 1];
    int deg = e - s;
    const float4* X = (const float4*)xsrc;

    // lanes prefetch up to 32 neighbor indices
    int myidx = (s + lane < e) ? csr[s + lane] : 0;

    float4 acc = make_float4(0.f, 0.f, 0.f, 0.f);
    int dcap = deg < 32 ? deg : 32;
    for (int b = 0; b < dcap; b += 8) {
        int   sj[8];
        float mk[8];
        float4 v[8];
#pragma unroll
        for (int j = 0; j < 8; j++) {
            int jj = b + j;
            int t_ = __shfl_sync(0xffffffffu, myidx, jj & 31);
            bool ok = (jj < dcap);
            sj[j] = ok ? t_ : 0;
            mk[j] = ok ? 1.f : 0.f;
        }
#pragma unroll
        for (int j = 0; j < 8; j++)
            v[j] = X[(size_t)sj[j] * (DD / 4) + lane];
#pragma unroll
        for (int j = 0; j < 8; j++) {
            acc.x += v[j].x * mk[j];
            acc.y += v[j].y * mk[j];
            acc.z += v[j].z * mk[j];
            acc.w += v[j].w * mk[j];
        }
    }
    // rare tail (deg > 32)
    for (int i = s + 32; i < e; i++) {
        int src = csr[i];
        float4 v = X[(size_t)src * (DD / 4) + lane];
        acc.x += v.x; acc.y += v.y; acc.z += v.z; acc.w += v.w;
    }

    float inv = 1.0f / fmaxf((float)deg, 1.0f);
    ((float4*)agg)[(size_t)w * (DD / 4) + lane] =
        make_float4(acc.x * inv, acc.y * inv, acc.z * inv, acc.w * inv);
}

// ---------------- small utility kernels ----------------
__global__ void prep_weights(const float* __restrict__ Wl,
                             const float* __restrict__ Wr,
                             float* __restrict__ Bext) {
    int i = blockIdx.x * blockDim.x + threadIdx.x;
    if (i >= 3 * 2 * K2 * DD) return;
    int j  = i % DD;
    int k  = (i / DD) % K2;
    int lt = i / (DD * K2);
    float v = (k < DD) ? Wl[((size_t)lt * DD + j) * DD + k]
                       : Wr[((size_t)lt * DD + j) * DD + (k - DD)];
    Bext[i] = v;
}

// ---------------- tf32 tensor-core fused SAGE GEMM ----------------
__device__ __forceinline__ uint32_t f2tf32(float f) {
    uint32_t r;
    asm("cvt.rna.tf32.f32 %0, %1;" : "=r"(r) : "f"(f));
    return r;
}

__global__ void __launch_bounds__(256)
gemm_sage_tc(const float* __restrict__ Aagg,
             const float* __restrict__ Xdst, const float* __restrict__ B,
             const float* __restrict__ bias, float* __restrict__ Cout,
             int nRows, int relu) {
    __shared__ uint32_t As[128][36];
    __shared__ uint32_t Bs[32][136];

    const int tid  = threadIdx.x;
    const int wid  = tid >> 5;
    const int lane = tid & 31;
    const int g    = lane >> 2;
    const int t    = lane & 3;
    const int m0   = (wid & 1) * 64;
    const int n0   = (wid >> 1) * 32;
    const int rowBase = blockIdx.x * 128;

    float acc[4][4][4];
#pragma unroll
    for (int im = 0; im < 4; im++)
#pragma unroll
        for (int in = 0; in < 4; in++)
#pragma unroll
            for (int q = 0; q < 4; q++) acc[im][in][q] = 0.f;

    for (int kt = 0; kt < K2; kt += 32) {
#pragma unroll
        for (int p = 0; p < 4; p++) {
            int f = tid + p * 256;
            int r = f >> 3;
            int q = f & 7;
            int gr = rowBase + r;
            if (gr >= nRows) gr = nRows - 1;
            int kg = kt + q * 4;
            const float* src = (kg < DD) ? (Aagg + (size_t)gr * DD + kg)
                                         : (Xdst + (size_t)gr * DD + (kg - DD));
            float4 v = *(const float4*)src;
            As[r][q * 4 + 0] = f2tf32(v.x);
            As[r][q * 4 + 1] = f2tf32(v.y);
            As[r][q * 4 + 2] = f2tf32(v.z);
            As[r][q * 4 + 3] = f2tf32(v.w);
        }
#pragma unroll
        for (int p = 0; p < 4; p++) {
            int f = tid + p * 256;
            int kr = f >> 5;
            int c  = f & 31;
            float4 v = *(const float4*)(B + (size_t)(kt + kr) * DD + c * 4);
            Bs[kr][c * 4 + 0] = f2tf32(v.x);
            Bs[kr][c * 4 + 1] = f2tf32(v.y);
            Bs[kr][c * 4 + 2] = f2tf32(v.z);
            Bs[kr][c * 4 + 3] = f2tf32(v.w);
        }
        __syncthreads();

#pragma unroll
        for (int kk = 0; kk < 32; kk += 8) {
            uint32_t a[4][4], b[4][2];
#pragma unroll
            for (int im = 0; im < 4; im++) {
                int rm = m0 + im * 16 + g;
                a[im][0] = As[rm][kk + t];
                a[im][1] = As[rm + 8][kk + t];
                a[im][2] = As[rm][kk + t + 4];
                a[im][3] = As[rm + 8][kk + t + 4];
            }
#pragma unroll
            for (int in = 0; in < 4; in++) {
                int cn = n0 + in * 8 + g;
                b[in][0] = Bs[kk + t][cn];
                b[in][1] = Bs[kk + t + 4][cn];
            }
#pragma unroll
            for (int im = 0; im < 4; im++)
#pragma unroll
                for (int in = 0; in < 4; in++) {
                    asm volatile(
                        "mma.sync.aligned.m16n8k8.row.col.f32.tf32.tf32.f32 "
                        "{%0,%1,%2,%3}, {%4,%5,%6,%7}, {%8,%9}, {%0,%1,%2,%3};"
                        : "+f"(acc[im][in][0]), "+f"(acc[im][in][1]),
                          "+f"(acc[im][in][2]), "+f"(acc[im][in][3])
                        : "r"(a[im][0]), "r"(a[im][1]), "r"(a[im][2]), "r"(a[im][3]),
                          "r"(b[in][0]), "r"(b[in][1]));
                }
        }
        __syncthreads();
    }

#pragma unroll
    for (int in = 0; in < 4; in++) {
        int col = n0 + in * 8 + 2 * t;
        float b0 = bias[col], b1 = bias[col + 1];
#pragma unroll
        for (int im = 0; im < 4; im++) {
            int r0 = rowBase + m0 + im * 16 + g;
            float v0 = acc[im][in][0] + b0;
            float v1 = acc[im][in][1] + b1;
            float v2 = acc[im][in][2] + b0;
            float v3 = acc[im][in][3] + b1;
            if (relu) {
                v0 = fmaxf(v0, 0.f); v1 = fmaxf(v1, 0.f);
                v2 = fmaxf(v2, 0.f); v3 = fmaxf(v3, 0.f);
            }
            if (r0 < nRows)
                *(float2*)(Cout + (size_t)r0 * DD + col) = make_float2(v0, v1);
            if (r0 + 8 < nRows)
                *(float2*)(Cout + (size_t)(r0 + 8) * DD + col) = make_float2(v2, v3);
        }
    }
}

// ---------------- launch ----------------
extern "C" void kernel_launch(void* const* d_in, const int* in_sizes, int n_in,
                              void* d_out, int out_size) {
    const float* x_m = (const float*)d_in[0];
    const float* x_t = (const float*)d_in[1];
    const float* Wl  = (const float*)d_in[2];
    const float* bl  = (const float*)d_in[3];
    const float* Wr  = (const float*)d_in[4];
    const void*  e_mt = d_in[5];
    const void*  e_tm = d_in[6];
    float* out = (float*)d_out;

    float *agg_t, *agg_m, *bm0, *bm1, *bt0, *bt1, *Bext;
    int *e32_mt, *e32_tm, *cnt_t, *cnt_m, *off_t, *off_m, *cur_t, *cur_m, *csr_t, *csr_m;
    cudaGetSymbolAddress((void**)&agg_t, g_agg_t);
    cudaGetSymbolAddress((void**)&agg_m, g_agg_m);
    cudaGetSymbolAddress((void**)&bm0, g_bm0);
    cudaGetSymbolAddress((void**)&bm1, g_bm1);
    cudaGetSymbolAddress((void**)&bt0, g_bt0);
    cudaGetSymbolAddress((void**)&bt1, g_bt1);
    cudaGetSymbolAddress((void**)&Bext, g_Bext);
    cudaGetSymbolAddress((void**)&e32_mt, g_e32_mt);
    cudaGetSymbolAddress((void**)&e32_tm, g_e32_tm);
    cudaGetSymbolAddress((void**)&cnt_t, g_cnt_t);
    cudaGetSymbolAddress((void**)&cnt_m, g_cnt_m);
    cudaGetSymbolAddress((void**)&off_t, g_off_t);
    cudaGetSymbolAddress((void**)&off_m, g_off_m);
    cudaGetSymbolAddress((void**)&cur_t, g_cur_t);
    cudaGetSymbolAddress((void**)&cur_m, g_cur_m);
    cudaGetSymbolAddress((void**)&csr_t, g_csr_t);
    cudaGetSymbolAddress((void**)&csr_m, g_csr_m);

    // ---- edge dtype detection + conversion to int32 ----
    detect_reset<<<1, 1>>>();
    detect_kernel<<<256, 256>>>((const unsigned*)e_mt);
    convert_kernel<<<CDIV(2 * NE, 256), 256>>>(e_mt, e32_mt);
    convert_kernel<<<CDIV(2 * NE, 256), 256>>>(e_tm, e32_tm);

    // ---- CSR build (once; reused by all 3 layers) ----
    zero_int<<<CDIV(NT, 256), 256>>>(cnt_t, NT);
    zero_int<<<CDIV(NM, 256), 256>>>(cnt_m, NM);
    hist_kernel<<<CDIV(NE, 256), 256>>>(e32_mt, cnt_t);
    hist_kernel<<<CDIV(NE, 256), 256>>>(e32_tm, cnt_m);
    scan_kernel<<<1, 1024>>>(cnt_t, off_t, cur_t, NT);
    scan_kernel<<<1, 1024>>>(cnt_m, off_m, cur_m, NM);
    fill_kernel<<<CDIV(NE, 256), 256>>>(e32_mt, cur_t, csr_t);
    fill_kernel<<<CDIV(NE, 256), 256>>>(e32_tm, cur_m, csr_m);

    // weight transpose/concat
    prep_weights<<<CDIV(3 * 2 * K2 * DD, 256), 256>>>(Wl, Wr, Bext);

    const float* xm_cur = x_m;
    const float* xt_cur = x_t;
    float* out_m = out;
    float* out_t = out + (size_t)NM * DD;

    const int aggBlocksT = CDIV(NT * 32, 256);
    const int aggBlocksM = CDIV(NM * 32, 256);

    for (int layer = 0; layer < 3; layer++) {
        float* xt_next = (layer == 2) ? out_t : ((layer == 0) ? bt0 : bt1);
        float* xm_next = (layer == 2) ? out_m : ((layer == 0) ? bm0 : bm1);
        int relu = (layer < 2) ? 1 : 0;

        // mean aggregation via CSR (pre-scaled by 1/deg), MLP-batched
        aggregate_csr<<<aggBlocksT, 256>>>(xm_cur, csr_t, off_t, agg_t, NT);
        aggregate_csr<<<aggBlocksM, 256>>>(xt_cur, csr_m, off_m, agg_m, NM);

        gemm_sage_tc<<<CDIV(NT, 128), 256>>>(
            agg_t, xt_cur,
            Bext + (size_t)(layer * 2 + 0) * K2 * DD,
            bl + (size_t)(layer * 2 + 0) * DD,
            xt_next, NT, relu);
        gemm_sage_tc<<<CDIV(NM, 128), 256>>>(
            agg_m, xm_cur,
            Bext + (size_t)(layer * 2 + 1) * K2 * DD,
            bl + (size_t)(layer * 2 + 1) * DD,
            xm_next, NM, relu);

        xm_cur = xm_next;
        xt_cur = xt_next;
    }
}

// round 7
// speedup vs baseline: 1.4350x; 1.0036x over previous
#include <cuda_runtime.h>
#include <cstdint>

// Problem constants
#define NM 100000
#define NT 100000
#define NE 400000
#define DD 128
#define K2 256   // concat K dim: [agg | x_dst]
#define NMAX 100000

#define CDIV(a,b) (((a)+(b)-1)/(b))

// ---------------- scratch (static __device__ allocations, 16B-aligned) ----
__device__ float4 g_agg_t[(size_t)NT * DD / 4];
__device__ float4 g_agg_m[(size_t)NM * DD / 4];
__device__ float4 g_bm0[(size_t)NM * DD / 4];
__device__ float4 g_bm1[(size_t)NM * DD / 4];
__device__ float4 g_bt0[(size_t)NT * DD / 4];
__device__ float4 g_bt1[(size_t)NT * DD / 4];
__device__ float4 g_Bext[3 * 2 * K2 * DD / 4];
__device__ int    g_e32_mt[2 * NE];
__device__ int    g_e32_tm[2 * NE];
__device__ int    g_is32;
// CSR scratch (x2 edge types)
__device__ int    g_cnt_t[NT];
__device__ int    g_cnt_m[NM];
__device__ int    g_off_t[NT + 1];
__device__ int    g_off_m[NM + 1];
__device__ int    g_cur_t[NT];
__device__ int    g_cur_m[NM];
__device__ int    g_csrs_t[NE];    // src ids sorted by dst (tracks as dst)
__device__ int    g_csrd_t[NE];    // matching dst ids
__device__ int    g_csrs_m[NE];
__device__ int    g_csrd_m[NE];
__device__ float  g_inv_t[NT];
__device__ float  g_inv_m[NM];

// ---------------- edge dtype detect + convert ----------------
__global__ void detect_reset() { g_is32 = 0; }

__global__ void detect_kernel(const unsigned* __restrict__ p) {
    int i = blockIdx.x * blockDim.x + threadIdx.x;
    unsigned v = 0;
    for (int w = i * 2 + 1; w < 2 * NE; w += gridDim.x * blockDim.x * 2)
        v |= p[w];
    if (__syncthreads_or(v != 0) && threadIdx.x == 0) atomicExch(&g_is32, 1);
}

__global__ void convert_kernel(const void* __restrict__ e, int* __restrict__ out) {
    int i = blockIdx.x * blockDim.x + threadIdx.x;
    if (i >= 2 * NE) return;
    int v;
    if (g_is32) v = ((const int*)e)[i];
    else        v = (int)((const long long*)e)[i];
    out[i] = min(max(v, 0), NMAX - 1);
}

// ---------------- CSR build ----------------
__global__ void zero_int(int* p, int n) {
    int i = blockIdx.x * blockDim.x + threadIdx.x;
    if (i < n) p[i] = 0;
}

__global__ void hist_kernel(const int* __restrict__ edge, int* __restrict__ cnt) {
    int i = blockIdx.x * blockDim.x + threadIdx.x;
    if (i < NE) atomicAdd(&cnt[edge[NE + i]], 1);
}

__global__ void scan_kernel(const int* __restrict__ cnt, int* __restrict__ off,
                            int* __restrict__ cur, int n) {
    __shared__ int partial[1024];
    const int tid = threadIdx.x;
    const int per = CDIV(n, 1024);
    const int base = tid * per;
    int sum = 0;
    for (int i = 0; i < per; i++) {
        int idx = base + i;
        if (idx < n) sum += cnt[idx];
    }
    partial[tid] = sum;
    __syncthreads();
    for (int d = 1; d < 1024; d <<= 1) {
        int t = (tid >= d) ? partial[tid - d] : 0;
        __syncthreads();
        partial[tid] += t;
        __syncthreads();
    }
    int run = partial[tid] - sum;
    for (int i = 0; i < per; i++) {
        int idx = base + i;
        if (idx < n) { off[idx] = run; cur[idx] = run; run += cnt[idx]; }
    }
    if (tid == 1023) off[n] = partial[1023];
}

__global__ void fill_kernel(const int* __restrict__ edge, int* __restrict__ cur,
                            int* __restrict__ csr_s, int* __restrict__ csr_d) {
    int i = blockIdx.x * blockDim.x + threadIdx.x;
    if (i >= NE) return;
    int src = edge[i];
    int dst = edge[NE + i];
    int pos = atomicAdd(&cur[dst], 1);
    csr_s[pos] = src;
    csr_d[pos] = dst;
}

__global__ void invert_from_cnt(const int* __restrict__ cnt, float* __restrict__ inv, int n) {
    int i = blockIdx.x * blockDim.x + threadIdx.x;
    if (i < n) inv[i] = 1.0f / (float)max(cnt[i], 1);
}

// ---------------- utility ----------------
__global__ void zero_kernel(float4* p, int n4) {
    int i = blockIdx.x * blockDim.x + threadIdx.x;
    int stride = gridDim.x * blockDim.x;
    float4 z = make_float4(0.f, 0.f, 0.f, 0.f);
    for (; i < n4; i += stride) p[i] = z;
}

__global__ void prep_weights(const float* __restrict__ Wl,
                             const float* __restrict__ Wr,
                             float* __restrict__ Bext) {
    int i = blockIdx.x * blockDim.x + threadIdx.x;
    if (i >= 3 * 2 * K2 * DD) return;
    int j  = i % DD;
    int k  = (i / DD) % K2;
    int lt = i / (DD * K2);
    float v = (k < DD) ? Wl[((size_t)lt * DD + j) * DD + k]
                       : Wr[((size_t)lt * DD + j) * DD + (k - DD)];
    Bext[i] = v;
}

// ---------------- sorted-edge scatter with in-warp run combining ----------
// Warp handles 8 consecutive dst-sorted edges: 8 independent predicated row
// loads (MLP=8), merge equal-dst runs in registers (warp-uniform branches),
// ONE pre-scaled RED per distinct dst run (~2.7x fewer REDG lane-ops).
__global__ void __launch_bounds__(256)
scatter_sorted(const float* __restrict__ xsrc,
               const int* __restrict__ csr_s,
               const int* __restrict__ csr_d,
               const float* __restrict__ inv,
               float* __restrict__ agg) {
    int w = (blockIdx.x * blockDim.x + threadIdx.x) >> 5;
    int lane = threadIdx.x & 31;
    int base = w * 8;
    if (base >= NE) return;
    const float4* X = (const float4*)xsrc;

    int my_s = 0, my_d = -1;
    if (lane < 8 && base + lane < NE) {
        my_s = csr_s[base + lane];
        my_d = csr_d[base + lane];
    }
    int srcs[8], dsts[8];
#pragma unroll
    for (int j = 0; j < 8; j++) {
        srcs[j] = __shfl_sync(0xffffffffu, my_s, j);
        dsts[j] = __shfl_sync(0xffffffffu, my_d, j);
    }
    float4 v[8];
#pragma unroll
    for (int j = 0; j < 8; j++) {
        v[j] = make_float4(0.f, 0.f, 0.f, 0.f);
        if (dsts[j] >= 0)
            v[j] = X[(size_t)srcs[j] * (DD / 4) + lane];
    }
    // serial run merge (warp-uniform control flow; dsts identical across lanes)
    float4 acc = v[0];
    int cur = dsts[0];
#pragma unroll
    for (int j = 1; j < 8; j++) {
        if (dsts[j] == cur) {
            acc.x += v[j].x; acc.y += v[j].y; acc.z += v[j].z; acc.w += v[j].w;
        } else {
            if (cur >= 0) {
                float s = inv[cur];
                float* a = agg + (size_t)cur * DD + lane * 4;
                asm volatile("red.global.add.v4.f32 [%0], {%1,%2,%3,%4};"
                             :: "l"(a), "f"(acc.x * s), "f"(acc.y * s),
                                "f"(acc.z * s), "f"(acc.w * s) : "memory");
            }
            acc = v[j];
            cur = dsts[j];
        }
    }
    if (cur >= 0) {
        float s = inv[cur];
        float* a = agg + (size_t)cur * DD + lane * 4;
        asm volatile("red.global.add.v4.f32 [%0], {%1,%2,%3,%4};"
                     :: "l"(a), "f"(acc.x * s), "f"(acc.y * s),
                        "f"(acc.z * s), "f"(acc.w * s) : "memory");
    }
}

// ---------------- tf32 tensor-core fused SAGE GEMM ----------------
__device__ __forceinline__ uint32_t f2tf32(float f) {
    uint32_t r;
    asm("cvt.rna.tf32.f32 %0, %1;" : "=r"(r) : "f"(f));
    return r;
}

__global__ void __launch_bounds__(256)
gemm_sage_tc(const float* __restrict__ Aagg,
             const float* __restrict__ Xdst, const float* __restrict__ B,
             const float* __restrict__ bias, float* __restrict__ Cout,
             int nRows, int relu) {
    __shared__ uint32_t As[128][36];
    __shared__ uint32_t Bs[32][136];

    const int tid  = threadIdx.x;
    const int wid  = tid >> 5;
    const int lane = tid & 31;
    const int g    = lane >> 2;
    const int t    = lane & 3;
    const int m0   = (wid & 1) * 64;
    const int n0   = (wid >> 1) * 32;
    const int rowBase = blockIdx.x * 128;

    float acc[4][4][4];
#pragma unroll
    for (int im = 0; im < 4; im++)
#pragma unroll
        for (int in = 0; in < 4; in++)
#pragma unroll
            for (int q = 0; q < 4; q++) acc[im][in][q] = 0.f;

    for (int kt = 0; kt < K2; kt += 32) {
#pragma unroll
        for (int p = 0; p < 4; p++) {
            int f = tid + p * 256;
            int r = f >> 3;
            int q = f & 7;
            int gr = rowBase + r;
            if (gr >= nRows) gr = nRows - 1;
            int kg = kt + q * 4;
            const float* src = (kg < DD) ? (Aagg + (size_t)gr * DD + kg)
                                         : (Xdst + (size_t)gr * DD + (kg - DD));
            float4 v = *(const float4*)src;
            As[r][q * 4 + 0] = f2tf32(v.x);
            As[r][q * 4 + 1] = f2tf32(v.y);
            As[r][q * 4 + 2] = f2tf32(v.z);
            As[r][q * 4 + 3] = f2tf32(v.w);
        }
#pragma unroll
        for (int p = 0; p < 4; p++) {
            int f = tid + p * 256;
            int kr = f >> 5;
            int c  = f & 31;
            float4 v = *(const float4*)(B + (size_t)(kt + kr) * DD + c * 4);
            Bs[kr][c * 4 + 0] = f2tf32(v.x);
            Bs[kr][c * 4 + 1] = f2tf32(v.y);
            Bs[kr][c * 4 + 2] = f2tf32(v.z);
            Bs[kr][c * 4 + 3] = f2tf32(v.w);
        }
        __syncthreads();

#pragma unroll
        for (int kk = 0; kk < 32; kk += 8) {
            uint32_t a[4][4], b[4][2];
#pragma unroll
            for (int im = 0; im < 4; im++) {
                int rm = m0 + im * 16 + g;
                a[im][0] = As[rm][kk + t];
                a[im][1] = As[rm + 8][kk + t];
                a[im][2] = As[rm][kk + t + 4];
                a[im][3] = As[rm + 8][kk + t + 4];
            }
#pragma unroll
            for (int in = 0; in < 4; in++) {
                int cn = n0 + in * 8 + g;
                b[in][0] = Bs[kk + t][cn];
                b[in][1] = Bs[kk + t + 4][cn];
            }
#pragma unroll
            for (int im = 0; im < 4; im++)
#pragma unroll
                for (int in = 0; in < 4; in++) {
                    asm volatile(
                        "mma.sync.aligned.m16n8k8.row.col.f32.tf32.tf32.f32 "
                        "{%0,%1,%2,%3}, {%4,%5,%6,%7}, {%8,%9}, {%0,%1,%2,%3};"
                        : "+f"(acc[im][in][0]), "+f"(acc[im][in][1]),
                          "+f"(acc[im][in][2]), "+f"(acc[im][in][3])
                        : "r"(a[im][0]), "r"(a[im][1]), "r"(a[im][2]), "r"(a[im][3]),
                          "r"(b[in][0]), "r"(b[in][1]));
                }
        }
        __syncthreads();
    }

#pragma unroll
    for (int in = 0; in < 4; in++) {
        int col = n0 + in * 8 + 2 * t;
        float b0 = bias[col], b1 = bias[col + 1];
#pragma unroll
        for (int im = 0; im < 4; im++) {
            int r0 = rowBase + m0 + im * 16 + g;
            float v0 = acc[im][in][0] + b0;
            float v1 = acc[im][in][1] + b1;
            float v2 = acc[im][in][2] + b0;
            float v3 = acc[im][in][3] + b1;
            if (relu) {
                v0 = fmaxf(v0, 0.f); v1 = fmaxf(v1, 0.f);
                v2 = fmaxf(v2, 0.f); v3 = fmaxf(v3, 0.f);
            }
            if (r0 < nRows)
                *(float2*)(Cout + (size_t)r0 * DD + col) = make_float2(v0, v1);
            if (r0 + 8 < nRows)
                *(float2*)(Cout + (size_t)(r0 + 8) * DD + col) = make_float2(v2, v3);
        }
    }
}

// ---------------- launch ----------------
extern "C" void kernel_launch(void* const* d_in, const int* in_sizes, int n_in,
                              void* d_out, int out_size) {
    const float* x_m = (const float*)d_in[0];
    const float* x_t = (const float*)d_in[1];
    const float* Wl  = (const float*)d_in[2];
    const float* bl  = (const float*)d_in[3];
    const float* Wr  = (const float*)d_in[4];
    const void*  e_mt = d_in[5];
    const void*  e_tm = d_in[6];
    float* out = (float*)d_out;

    float *agg_t, *agg_m, *bm0, *bm1, *bt0, *bt1, *Bext, *inv_t, *inv_m;
    int *e32_mt, *e32_tm, *cnt_t, *cnt_m, *off_t, *off_m, *cur_t, *cur_m;
    int *csrs_t, *csrd_t, *csrs_m, *csrd_m;
    cudaGetSymbolAddress((void**)&agg_t, g_agg_t);
    cudaGetSymbolAddress((void**)&agg_m, g_agg_m);
    cudaGetSymbolAddress((void**)&bm0, g_bm0);
    cudaGetSymbolAddress((void**)&bm1, g_bm1);
    cudaGetSymbolAddress((void**)&bt0, g_bt0);
    cudaGetSymbolAddress((void**)&bt1, g_bt1);
    cudaGetSymbolAddress((void**)&Bext, g_Bext);
    cudaGetSymbolAddress((void**)&e32_mt, g_e32_mt);
    cudaGetSymbolAddress((void**)&e32_tm, g_e32_tm);
    cudaGetSymbolAddress((void**)&cnt_t, g_cnt_t);
    cudaGetSymbolAddress((void**)&cnt_m, g_cnt_m);
    cudaGetSymbolAddress((void**)&off_t, g_off_t);
    cudaGetSymbolAddress((void**)&off_m, g_off_m);
    cudaGetSymbolAddress((void**)&cur_t, g_cur_t);
    cudaGetSymbolAddress((void**)&cur_m, g_cur_m);
    cudaGetSymbolAddress((void**)&csrs_t, g_csrs_t);
    cudaGetSymbolAddress((void**)&csrd_t, g_csrd_t);
    cudaGetSymbolAddress((void**)&csrs_m, g_csrs_m);
    cudaGetSymbolAddress((void**)&csrd_m, g_csrd_m);
    cudaGetSymbolAddress((void**)&inv_t, g_inv_t);
    cudaGetSymbolAddress((void**)&inv_m, g_inv_m);

    // ---- edge dtype detection + conversion to int32 ----
    detect_reset<<<1, 1>>>();
    detect_kernel<<<256, 256>>>((const unsigned*)e_mt);
    convert_kernel<<<CDIV(2 * NE, 256), 256>>>(e_mt, e32_mt);
    convert_kernel<<<CDIV(2 * NE, 256), 256>>>(e_tm, e32_tm);

    // ---- CSR-sorted edge lists + inverse degrees (once) ----
    zero_int<<<CDIV(NT, 256), 256>>>(cnt_t, NT);
    zero_int<<<CDIV(NM, 256), 256>>>(cnt_m, NM);
    hist_kernel<<<CDIV(NE, 256), 256>>>(e32_mt, cnt_t);
    hist_kernel<<<CDIV(NE, 256), 256>>>(e32_tm, cnt_m);
    scan_kernel<<<1, 1024>>>(cnt_t, off_t, cur_t, NT);
    scan_kernel<<<1, 1024>>>(cnt_m, off_m, cur_m, NM);
    fill_kernel<<<CDIV(NE, 256), 256>>>(e32_mt, cur_t, csrs_t, csrd_t);
    fill_kernel<<<CDIV(NE, 256), 256>>>(e32_tm, cur_m, csrs_m, csrd_m);
    invert_from_cnt<<<CDIV(NT, 256), 256>>>(cnt_t, inv_t, NT);
    invert_from_cnt<<<CDIV(NM, 256), 256>>>(cnt_m, inv_m, NM);

    // weight transpose/concat
    prep_weights<<<CDIV(3 * 2 * K2 * DD, 256), 256>>>(Wl, Wr, Bext);

    const float* xm_cur = x_m;
    const float* xt_cur = x_t;
    float* out_m = out;
    float* out_t = out + (size_t)NM * DD;

    const int scatterBlocks = CDIV(CDIV(NE, 8) * 32, 256);
    const int aggT4 = NT * DD / 4;
    const int aggM4 = NM * DD / 4;

    for (int layer = 0; layer < 3; layer++) {
        float* xt_next = (layer == 2) ? out_t : ((layer == 0) ? bt0 : bt1);
        float* xm_next = (layer == 2) ? out_m : ((layer == 0) ? bm0 : bm1);
        int relu = (layer < 2) ? 1 : 0;

        // edge type 0: musicians -> tracks
        zero_kernel<<<4096, 256>>>((float4*)agg_t, aggT4);
        scatter_sorted<<<scatterBlocks, 256>>>(xm_cur, csrs_t, csrd_t, inv_t, agg_t);
        // edge type 1: tracks -> musicians
        zero_kernel<<<4096, 256>>>((float4*)agg_m, aggM4);
        scatter_sorted<<<scatterBlocks, 256>>>(xt_cur, csrs_m, csrd_m, inv_m, agg_m);

        gemm_sage_tc<<<CDIV(NT, 128), 256>>>(
            agg_t, xt_cur,
            Bext + (size_t)(layer * 2 + 0) * K2 * DD,
            bl + (size_t)(layer * 2 + 0) * DD,
            xt_next, NT, relu);
        gemm_sage_tc<<<CDIV(NM, 128), 256>>>(
            agg_m, xm_cur,
            Bext + (size_t)(layer * 2 + 1) * K2 * DD,
            bl + (size_t)(layer * 2 + 1) * DD,
            xm_next, NM, relu);

        xm_cur = xm_next;
        xt_cur = xt_next;
    }
}

// round 8
// speedup vs baseline: 1.8413x; 1.2831x over previous
#include <cuda_runtime.h>
#include <cstdint>

// Problem constants
#define NM 100000
#define NT 100000
#define NE 400000
#define DD 128
#define K2 256   // concat K dim: [agg | x_dst]
#define NMAX 100000

#define CDIV(a,b) (((a)+(b)-1)/(b))

// ---------------- scratch (static __device__ allocations, 16B-aligned) ----
__device__ float4 g_agg_t[(size_t)NT * DD / 4];
__device__ float4 g_agg_m[(size_t)NM * DD / 4];
__device__ float4 g_bm0[(size_t)NM * DD / 4];
__device__ float4 g_bm1[(size_t)NM * DD / 4];
__device__ float4 g_bt0[(size_t)NT * DD / 4];
__device__ float4 g_bt1[(size_t)NT * DD / 4];
__device__ float4 g_inv_t[NT / 4];
__device__ float4 g_inv_m[NM / 4];
__device__ float4 g_Bext[3 * 2 * K2 * DD / 4];
__device__ int    g_e32_mt[2 * NE];
__device__ int    g_e32_tm[2 * NE];
__device__ int    g_is32;

// ---------------- edge dtype detect + convert ----------------
__global__ void detect_reset() { g_is32 = 0; }

__global__ void detect_kernel(const unsigned* __restrict__ p) {
    int i = blockIdx.x * blockDim.x + threadIdx.x;
    unsigned v = 0;
    for (int w = i * 2 + 1; w < 2 * NE; w += gridDim.x * blockDim.x * 2)
        v |= p[w];
    if (__syncthreads_or(v != 0) && threadIdx.x == 0) atomicExch(&g_is32, 1);
}

__global__ void convert_kernel(const void* __restrict__ e, int* __restrict__ out) {
    int i = blockIdx.x * blockDim.x + threadIdx.x;
    if (i >= 2 * NE) return;
    int v;
    if (g_is32) v = ((const int*)e)[i];
    else        v = (int)((const long long*)e)[i];
    out[i] = min(max(v, 0), NMAX - 1);
}

// ---------------- small utility kernels ----------------
// zero both agg buffers in one launch
__global__ void zero_two(float4* p0, int n0, float4* p1, int n1) {
    int i = blockIdx.x * blockDim.x + threadIdx.x;
    int stride = gridDim.x * blockDim.x;
    float4 z = make_float4(0.f, 0.f, 0.f, 0.f);
    for (int k = i; k < n0; k += stride) p0[k] = z;
    for (int k = i; k < n1; k += stride) p1[k] = z;
}

__global__ void zero_kernel(float4* p, int n4) {
    int i = blockIdx.x * blockDim.x + threadIdx.x;
    int stride = gridDim.x * blockDim.x;
    float4 z = make_float4(0.f, 0.f, 0.f, 0.f);
    for (; i < n4; i += stride) p[i] = z;
}

__global__ void prep_weights(const float* __restrict__ Wl,
                             const float* __restrict__ Wr,
                             float* __restrict__ Bext) {
    int i = blockIdx.x * blockDim.x + threadIdx.x;
    if (i >= 3 * 2 * K2 * DD) return;
    int j  = i % DD;
    int k  = (i / DD) % K2;
    int lt = i / (DD * K2);
    float v = (k < DD) ? Wl[((size_t)lt * DD + j) * DD + k]
                       : Wr[((size_t)lt * DD + j) * DD + (k - DD)];
    Bext[i] = v;
}

__global__ void count_kernel(const int* __restrict__ edge,
                             float* __restrict__ cnt) {
    int i = blockIdx.x * blockDim.x + threadIdx.x;
    if (i < NE) atomicAdd(&cnt[edge[NE + i]], 1.0f);
}

__global__ void invert_kernel(float* __restrict__ c, int n) {
    int i = blockIdx.x * blockDim.x + threadIdx.x;
    if (i < n) c[i] = 1.0f / fmaxf(c[i], 1.0f);
}

// ---------------- scatter via TMA bulk-reduce ----------------
// Warp handles 4 edges: 32 lanes stage each 512B row into smem, then one
// elected lane issues ONE cp.reduce.async.bulk per edge (vs 32 red.v4 lane
// ops). Issue count per launch: 12.8M -> 400k.
#define EPW 4   // edges per warp
__global__ void __launch_bounds__(256)
scatter_bulk(const float* __restrict__ xsrc,
             const int* __restrict__ edge,
             float* __restrict__ agg) {
    __shared__ __align__(16) float smem[8][EPW][DD];   // 8 warps * 4 * 512B = 16KB
    const int wInB = threadIdx.x >> 5;
    const int lane = threadIdx.x & 31;
    const int gw = (blockIdx.x * blockDim.x + threadIdx.x) >> 5;
    const int base = gw * EPW;
    if (base >= NE) return;
    const int nE = min(EPW, NE - base);
    const float4* X = (const float4*)xsrc;

#pragma unroll
    for (int j = 0; j < EPW; j++) {
        if (j < nE) {
            int src = edge[base + j];
            ((float4*)smem[wInB][j])[lane] = X[(size_t)src * (DD / 4) + lane];
        }
    }
    __syncwarp();
    if (lane == 0) {
        asm volatile("fence.proxy.async.shared::cta;" ::: "memory");
#pragma unroll
        for (int j = 0; j < EPW; j++) {
            if (j < nE) {
                int dst = edge[NE + base + j];
                float* gp = agg + (size_t)dst * DD;
                uint32_t sa;
                asm("{ .reg .u64 t; cvta.to.shared.u64 t, %1; cvt.u32.u64 %0, t; }"
                    : "=r"(sa) : "l"(&smem[wInB][j][0]));
                asm volatile(
                    "cp.reduce.async.bulk.global.shared::cta.bulk_group.add.f32 "
                    "[%0], [%1], %2;"
                    :: "l"(gp), "r"(sa), "r"(DD * 4) : "memory");
            }
        }
        asm volatile("cp.async.bulk.commit_group;" ::: "memory");
        asm volatile("cp.async.bulk.wait_group 0;" ::: "memory");
    }
}

// ---------------- tf32 tensor-core fused SAGE GEMM (R4-proven) ------------
// C[i,j] = sum_{k<128} (agg[i,k]*inv[i])*B[k,j] + sum_k x[i,k]*B[128+k,j] + bias[j]
__device__ __forceinline__ uint32_t f2tf32(float f) {
    uint32_t r;
    asm("cvt.rna.tf32.f32 %0, %1;" : "=r"(r) : "f"(f));
    return r;
}

__global__ void __launch_bounds__(256)
gemm_sage_tc(const float* __restrict__ Aagg, const float* __restrict__ inv,
             const float* __restrict__ Xdst, const float* __restrict__ B,
             const float* __restrict__ bias, float* __restrict__ Cout,
             int nRows, int relu) {
    __shared__ uint32_t As[128][36];
    __shared__ uint32_t Bs[32][136];

    const int tid  = threadIdx.x;
    const int wid  = tid >> 5;
    const int lane = tid & 31;
    const int g    = lane >> 2;
    const int t    = lane & 3;
    const int m0   = (wid & 1) * 64;
    const int n0   = (wid >> 1) * 32;
    const int rowBase = blockIdx.x * 128;

    float acc[4][4][4];
#pragma unroll
    for (int im = 0; im < 4; im++)
#pragma unroll
        for (int in = 0; in < 4; in++)
#pragma unroll
            for (int q = 0; q < 4; q++) acc[im][in][q] = 0.f;

    for (int kt = 0; kt < K2; kt += 32) {
#pragma unroll
        for (int p = 0; p < 4; p++) {
            int f = tid + p * 256;
            int r = f >> 3;
            int q = f & 7;
            int gr = rowBase + r;
            if (gr >= nRows) gr = nRows - 1;
            int kg = kt + q * 4;
            float s;
            const float* src;
            if (kg < DD) { src = Aagg + (size_t)gr * DD + kg; s = inv[gr]; }
            else         { src = Xdst + (size_t)gr * DD + (kg - DD); s = 1.0f; }
            float4 v = *(const float4*)src;
            As[r][q * 4 + 0] = f2tf32(v.x * s);
            As[r][q * 4 + 1] = f2tf32(v.y * s);
            As[r][q * 4 + 2] = f2tf32(v.z * s);
            As[r][q * 4 + 3] = f2tf32(v.w * s);
        }
#pragma unroll
        for (int p = 0; p < 4; p++) {
            int f = tid + p * 256;
            int kr = f >> 5;
            int c  = f & 31;
            float4 v = *(const float4*)(B + (size_t)(kt + kr) * DD + c * 4);
            Bs[kr][c * 4 + 0] = f2tf32(v.x);
            Bs[kr][c * 4 + 1] = f2tf32(v.y);
            Bs[kr][c * 4 + 2] = f2tf32(v.z);
            Bs[kr][c * 4 + 3] = f2tf32(v.w);
        }
        __syncthreads();

#pragma unroll
        for (int kk = 0; kk < 32; kk += 8) {
            uint32_t a[4][4], b[4][2];
#pragma unroll
            for (int im = 0; im < 4; im++) {
                int rm = m0 + im * 16 + g;
                a[im][0] = As[rm][kk + t];
                a[im][1] = As[rm + 8][kk + t];
                a[im][2] = As[rm][kk + t + 4];
                a[im][3] = As[rm + 8][kk + t + 4];
            }
#pragma unroll
            for (int in = 0; in < 4; in++) {
                int cn = n0 + in * 8 + g;
                b[in][0] = Bs[kk + t][cn];
                b[in][1] = Bs[kk + t + 4][cn];
            }
#pragma unroll
            for (int im = 0; im < 4; im++)
#pragma unroll
                for (int in = 0; in < 4; in++) {
                    asm volatile(
                        "mma.sync.aligned.m16n8k8.row.col.f32.tf32.tf32.f32 "
                        "{%0,%1,%2,%3}, {%4,%5,%6,%7}, {%8,%9}, {%0,%1,%2,%3};"
                        : "+f"(acc[im][in][0]), "+f"(acc[im][in][1]),
                          "+f"(acc[im][in][2]), "+f"(acc[im][in][3])
                        : "r"(a[im][0]), "r"(a[im][1]), "r"(a[im][2]), "r"(a[im][3]),
                          "r"(b[in][0]), "r"(b[in][1]));
                }
        }
        __syncthreads();
    }

#pragma unroll
    for (int in = 0; in < 4; in++) {
        int col = n0 + in * 8 + 2 * t;
        float b0 = bias[col], b1 = bias[col + 1];
#pragma unroll
        for (int im = 0; im < 4; im++) {
            int r0 = rowBase + m0 + im * 16 + g;
            float v0 = acc[im][in][0] + b0;
            float v1 = acc[im][in][1] + b1;
            float v2 = acc[im][in][2] + b0;
            float v3 = acc[im][in][3] + b1;
            if (relu) {
                v0 = fmaxf(v0, 0.f); v1 = fmaxf(v1, 0.f);
                v2 = fmaxf(v2, 0.f); v3 = fmaxf(v3, 0.f);
            }
            if (r0 < nRows)
                *(float2*)(Cout + (size_t)r0 * DD + col) = make_float2(v0, v1);
            if (r0 + 8 < nRows)
                *(float2*)(Cout + (size_t)(r0 + 8) * DD + col) = make_float2(v2, v3);
        }
    }
}

// ---------------- launch ----------------
extern "C" void kernel_launch(void* const* d_in, const int* in_sizes, int n_in,
                              void* d_out, int out_size) {
    const float* x_m = (const float*)d_in[0];
    const float* x_t = (const float*)d_in[1];
    const float* Wl  = (const float*)d_in[2];
    const float* bl  = (const float*)d_in[3];
    const float* Wr  = (const float*)d_in[4];
    const void*  e_mt = d_in[5];
    const void*  e_tm = d_in[6];
    float* out = (float*)d_out;

    float *agg_t, *agg_m, *bm0, *bm1, *bt0, *bt1, *inv_t, *inv_m, *Bext;
    int *e32_mt, *e32_tm;
    cudaGetSymbolAddress((void**)&agg_t, g_agg_t);
    cudaGetSymbolAddress((void**)&agg_m, g_agg_m);
    cudaGetSymbolAddress((void**)&bm0, g_bm0);
    cudaGetSymbolAddress((void**)&bm1, g_bm1);
    cudaGetSymbolAddress((void**)&bt0, g_bt0);
    cudaGetSymbolAddress((void**)&bt1, g_bt1);
    cudaGetSymbolAddress((void**)&inv_t, g_inv_t);
    cudaGetSymbolAddress((void**)&inv_m, g_inv_m);
    cudaGetSymbolAddress((void**)&Bext, g_Bext);
    cudaGetSymbolAddress((void**)&e32_mt, g_e32_mt);
    cudaGetSymbolAddress((void**)&e32_tm, g_e32_tm);

    const int scatterBlocks = CDIV(CDIV(NE, EPW) * 32, 256);
    const int aggT4 = NT * DD / 4;
    const int aggM4 = NM * DD / 4;

    // launches 1-4: edge dtype detection + conversion
    detect_reset<<<1, 1>>>();
    detect_kernel<<<256, 256>>>((const unsigned*)e_mt);
    convert_kernel<<<CDIV(2 * NE, 256), 256>>>(e_mt, e32_mt);
    convert_kernel<<<CDIV(2 * NE, 256), 256>>>(e_tm, e32_tm);

    // launch 5: zero both agg buffers (layer 0)
    zero_two<<<4096, 256>>>((float4*)agg_t, aggT4, (float4*)agg_m, aggM4);
    // launch 6: scatter (ncu -s 5 -c 1 captures THIS one)
    scatter_bulk<<<scatterBlocks, 256>>>(x_m, e32_mt, agg_t);
    scatter_bulk<<<scatterBlocks, 256>>>(x_t, e32_tm, agg_m);

    // degree counts -> inverse (reused across layers)
    zero_kernel<<<128, 256>>>((float4*)inv_t, NT / 4);
    zero_kernel<<<128, 256>>>((float4*)inv_m, NM / 4);
    count_kernel<<<CDIV(NE, 256), 256>>>(e32_mt, (float*)inv_t);
    count_kernel<<<CDIV(NE, 256), 256>>>(e32_tm, (float*)inv_m);
    invert_kernel<<<CDIV(NT, 256), 256>>>((float*)inv_t, NT);
    invert_kernel<<<CDIV(NM, 256), 256>>>((float*)inv_m, NM);

    // weight transpose/concat
    prep_weights<<<CDIV(3 * 2 * K2 * DD, 256), 256>>>(Wl, Wr, Bext);

    const float* xm_cur = x_m;
    const float* xt_cur = x_t;
    float* out_m = out;
    float* out_t = out + (size_t)NM * DD;

    for (int layer = 0; layer < 3; layer++) {
        float* xt_next = (layer == 2) ? out_t : ((layer == 0) ? bt0 : bt1);
        float* xm_next = (layer == 2) ? out_m : ((layer == 0) ? bm0 : bm1);
        int relu = (layer < 2) ? 1 : 0;

        if (layer > 0) {   // layer 0 aggregation already issued above
            zero_two<<<4096, 256>>>((float4*)agg_t, aggT4, (float4*)agg_m, aggM4);
            scatter_bulk<<<scatterBlocks, 256>>>(xm_cur, e32_mt, agg_t);
            scatter_bulk<<<scatterBlocks, 256>>>(xt_cur, e32_tm, agg_m);
        }

        gemm_sage_tc<<<CDIV(NT, 128), 256>>>(
            agg_t, (float*)inv_t, xt_cur,
            Bext + (size_t)(layer * 2 + 0) * K2 * DD,
            bl + (size_t)(layer * 2 + 0) * DD,
            xt_next, NT, relu);
        gemm_sage_tc<<<CDIV(NM, 128), 256>>>(
            agg_m, (float*)inv_m, xm_cur,
            Bext + (size_t)(layer * 2 + 1) * K2 * DD,
            bl + (size_t)(layer * 2 + 1) * DD,
            xm_next, NM, relu);

        xm_cur = xm_next;
        xt_cur = xt_next;
    }
}

// round 9
// speedup vs baseline: 1.9333x; 1.0500x over previous
#include <cuda_runtime.h>
#include <cstdint>

// Problem constants
#define NM 100000
#define NT 100000
#define NE 400000
#define DD 128
#define K2 256   // concat K dim: [agg | x_dst]
#define NMAX 100000

#define CDIV(a,b) (((a)+(b)-1)/(b))

// ---------------- scratch (static __device__ allocations, 16B-aligned) ----
__device__ float4 g_agg_t[(size_t)NT * DD / 4];
__device__ float4 g_agg_m[(size_t)NM * DD / 4];
__device__ float4 g_bm0[(size_t)NM * DD / 4];
__device__ float4 g_bm1[(size_t)NM * DD / 4];
__device__ float4 g_bt0[(size_t)NT * DD / 4];
__device__ float4 g_bt1[(size_t)NT * DD / 4];
__device__ float4 g_inv_t[NT / 4];
__device__ float4 g_inv_m[NM / 4];
__device__ float4 g_Bext[3 * 2 * K2 * DD / 4];
__device__ int    g_e32_mt[2 * NE];
__device__ int    g_e32_tm[2 * NE];
__device__ int    g_is32;

// ---------------- edge dtype detect + convert ----------------
__global__ void detect_reset() { g_is32 = 0; }

__global__ void detect_kernel(const unsigned* __restrict__ p) {
    int i = blockIdx.x * blockDim.x + threadIdx.x;
    unsigned v = 0;
    for (int w = i * 2 + 1; w < 2 * NE; w += gridDim.x * blockDim.x * 2)
        v |= p[w];
    if (__syncthreads_or(v != 0) && threadIdx.x == 0) atomicExch(&g_is32, 1);
}

__global__ void convert_kernel(const void* __restrict__ e, int* __restrict__ out) {
    int i = blockIdx.x * blockDim.x + threadIdx.x;
    if (i >= 2 * NE) return;
    int v;
    if (g_is32) v = ((const int*)e)[i];
    else        v = (int)((const long long*)e)[i];
    out[i] = min(max(v, 0), NMAX - 1);
}

// ---------------- small utility kernels ----------------
__global__ void zero_two(float4* p0, int n0, float4* p1, int n1) {
    int i = blockIdx.x * blockDim.x + threadIdx.x;
    int stride = gridDim.x * blockDim.x;
    float4 z = make_float4(0.f, 0.f, 0.f, 0.f);
    for (int k = i; k < n0; k += stride) p0[k] = z;
    for (int k = i; k < n1; k += stride) p1[k] = z;
}

__global__ void zero_kernel(float4* p, int n4) {
    int i = blockIdx.x * blockDim.x + threadIdx.x;
    int stride = gridDim.x * blockDim.x;
    float4 z = make_float4(0.f, 0.f, 0.f, 0.f);
    for (; i < n4; i += stride) p[i] = z;
}

__global__ void prep_weights(const float* __restrict__ Wl,
                             const float* __restrict__ Wr,
                             float* __restrict__ Bext) {
    int i = blockIdx.x * blockDim.x + threadIdx.x;
    if (i >= 3 * 2 * K2 * DD) return;
    int j  = i % DD;
    int k  = (i / DD) % K2;
    int lt = i / (DD * K2);
    float v = (k < DD) ? Wl[((size_t)lt * DD + j) * DD + k]
                       : Wr[((size_t)lt * DD + j) * DD + (k - DD)];
    Bext[i] = v;
}

__global__ void count_kernel(const int* __restrict__ edge,
                             float* __restrict__ cnt) {
    int i = blockIdx.x * blockDim.x + threadIdx.x;
    if (i < NE) atomicAdd(&cnt[edge[NE + i]], 1.0f);
}

__global__ void invert_kernel(float* __restrict__ c, int n) {
    int i = blockIdx.x * blockDim.x + threadIdx.x;
    if (i < n) c[i] = 1.0f / fmaxf(c[i], 1.0f);
}

// ---------------- scatter via TMA bulk-reduce ----------------
#define EPW 4   // edges per warp
__global__ void __launch_bounds__(256)
scatter_bulk(const float* __restrict__ xsrc,
             const int* __restrict__ edge,
             float* __restrict__ agg) {
    __shared__ __align__(16) float smem[8][EPW][DD];   // 16KB
    const int wInB = threadIdx.x >> 5;
    const int lane = threadIdx.x & 31;
    const int gw = (blockIdx.x * blockDim.x + threadIdx.x) >> 5;
    const int base = gw * EPW;
    if (base >= NE) return;
    const int nE = min(EPW, NE - base);
    const float4* X = (const float4*)xsrc;

#pragma unroll
    for (int j = 0; j < EPW; j++) {
        if (j < nE) {
            int src = edge[base + j];
            ((float4*)smem[wInB][j])[lane] = X[(size_t)src * (DD / 4) + lane];
        }
    }
    __syncwarp();
    if (lane == 0) {
        asm volatile("fence.proxy.async.shared::cta;" ::: "memory");
#pragma unroll
        for (int j = 0; j < EPW; j++) {
            if (j < nE) {
                int dst = edge[NE + base + j];
                float* gp = agg + (size_t)dst * DD;
                uint32_t sa;
                asm("{ .reg .u64 t; cvta.to.shared.u64 t, %1; cvt.u32.u64 %0, t; }"
                    : "=r"(sa) : "l"(&smem[wInB][j][0]));
                asm volatile(
                    "cp.reduce.async.bulk.global.shared::cta.bulk_group.add.f32 "
                    "[%0], [%1], %2;"
                    :: "l"(gp), "r"(sa), "r"(DD * 4) : "memory");
            }
        }
        asm volatile("cp.async.bulk.commit_group;" ::: "memory");
        asm volatile("cp.async.bulk.wait_group 0;" ::: "memory");
    }
}

// ---------------- tf32 tensor-core fused SAGE GEMM ----------------
__device__ __forceinline__ uint32_t f2tf32(float f) {
    uint32_t r;
    asm("cvt.rna.tf32.f32 %0, %1;" : "=r"(r) : "f"(f));
    return r;
}

__global__ void __launch_bounds__(256)
gemm_sage_tc(const float* __restrict__ Aagg, const float* __restrict__ inv,
             const float* __restrict__ Xdst, const float* __restrict__ B,
             const float* __restrict__ bias, float* __restrict__ Cout,
             int nRows, int relu) {
    __shared__ uint32_t As[128][36];
    __shared__ uint32_t Bs[32][136];

    const int tid  = threadIdx.x;
    const int wid  = tid >> 5;
    const int lane = tid & 31;
    const int g    = lane >> 2;
    const int t    = lane & 3;
    const int m0   = (wid & 1) * 64;
    const int n0   = (wid >> 1) * 32;
    const int rowBase = blockIdx.x * 128;

    float acc[4][4][4];
#pragma unroll
    for (int im = 0; im < 4; im++)
#pragma unroll
        for (int in = 0; in < 4; in++)
#pragma unroll
            for (int q = 0; q < 4; q++) acc[im][in][q] = 0.f;

    for (int kt = 0; kt < K2; kt += 32) {
#pragma unroll
        for (int p = 0; p < 4; p++) {
            int f = tid + p * 256;
            int r = f >> 3;
            int q = f & 7;
            int gr = rowBase + r;
            if (gr >= nRows) gr = nRows - 1;
            int kg = kt + q * 4;
            float s;
            const float* src;
            if (kg < DD) { src = Aagg + (size_t)gr * DD + kg; s = inv[gr]; }
            else         { src = Xdst + (size_t)gr * DD + (kg - DD); s = 1.0f; }
            float4 v = *(const float4*)src;
            As[r][q * 4 + 0] = f2tf32(v.x * s);
            As[r][q * 4 + 1] = f2tf32(v.y * s);
            As[r][q * 4 + 2] = f2tf32(v.z * s);
            As[r][q * 4 + 3] = f2tf32(v.w * s);
        }
#pragma unroll
        for (int p = 0; p < 4; p++) {
            int f = tid + p * 256;
            int kr = f >> 5;
            int c  = f & 31;
            float4 v = *(const float4*)(B + (size_t)(kt + kr) * DD + c * 4);
            Bs[kr][c * 4 + 0] = f2tf32(v.x);
            Bs[kr][c * 4 + 1] = f2tf32(v.y);
            Bs[kr][c * 4 + 2] = f2tf32(v.z);
            Bs[kr][c * 4 + 3] = f2tf32(v.w);
        }
        __syncthreads();

#pragma unroll
        for (int kk = 0; kk < 32; kk += 8) {
            uint32_t a[4][4], b[4][2];
#pragma unroll
            for (int im = 0; im < 4; im++) {
                int rm = m0 + im * 16 + g;
                a[im][0] = As[rm][kk + t];
                a[im][1] = As[rm + 8][kk + t];
                a[im][2] = As[rm][kk + t + 4];
                a[im][3] = As[rm + 8][kk + t + 4];
            }
#pragma unroll
            for (int in = 0; in < 4; in++) {
                int cn = n0 + in * 8 + g;
                b[in][0] = Bs[kk + t][cn];
                b[in][1] = Bs[kk + t + 4][cn];
            }
#pragma unroll
            for (int im = 0; im < 4; im++)
#pragma unroll
                for (int in = 0; in < 4; in++) {
                    asm volatile(
                        "mma.sync.aligned.m16n8k8.row.col.f32.tf32.tf32.f32 "
                        "{%0,%1,%2,%3}, {%4,%5,%6,%7}, {%8,%9}, {%0,%1,%2,%3};"
                        : "+f"(acc[im][in][0]), "+f"(acc[im][in][1]),
                          "+f"(acc[im][in][2]), "+f"(acc[im][in][3])
                        : "r"(a[im][0]), "r"(a[im][1]), "r"(a[im][2]), "r"(a[im][3]),
                          "r"(b[in][0]), "r"(b[in][1]));
                }
        }
        __syncthreads();
    }

#pragma unroll
    for (int in = 0; in < 4; in++) {
        int col = n0 + in * 8 + 2 * t;
        float b0 = bias[col], b1 = bias[col + 1];
#pragma unroll
        for (int im = 0; im < 4; im++) {
            int r0 = rowBase + m0 + im * 16 + g;
            float v0 = acc[im][in][0] + b0;
            float v1 = acc[im][in][1] + b1;
            float v2 = acc[im][in][2] + b0;
            float v3 = acc[im][in][3] + b1;
            if (relu) {
                v0 = fmaxf(v0, 0.f); v1 = fmaxf(v1, 0.f);
                v2 = fmaxf(v2, 0.f); v3 = fmaxf(v3, 0.f);
            }
            if (r0 < nRows)
                *(float2*)(Cout + (size_t)r0 * DD + col) = make_float2(v0, v1);
            if (r0 + 8 < nRows)
                *(float2*)(Cout + (size_t)(r0 + 8) * DD + col) = make_float2(v2, v3);
        }
    }
}

// ---------------- launch: two-stream fork/join pipeline ----------------
extern "C" void kernel_launch(void* const* d_in, const int* in_sizes, int n_in,
                              void* d_out, int out_size) {
    // one-time stream/event creation (first call is the uncaptured
    // correctness run; graph capture reuses these)
    static bool s_init = false;
    static cudaStream_t sT, sM;
    static cudaEvent_t evFork, evGT[3], evGM[3];
    if (!s_init) {
        cudaStreamCreateWithFlags(&sT, cudaStreamNonBlocking);
        cudaStreamCreateWithFlags(&sM, cudaStreamNonBlocking);
        cudaEventCreateWithFlags(&evFork, cudaEventDisableTiming);
        for (int i = 0; i < 3; i++) {
            cudaEventCreateWithFlags(&evGT[i], cudaEventDisableTiming);
            cudaEventCreateWithFlags(&evGM[i], cudaEventDisableTiming);
        }
        s_init = true;
    }

    const float* x_m = (const float*)d_in[0];
    const float* x_t = (const float*)d_in[1];
    const float* Wl  = (const float*)d_in[2];
    const float* bl  = (const float*)d_in[3];
    const float* Wr  = (const float*)d_in[4];
    const void*  e_mt = d_in[5];
    const void*  e_tm = d_in[6];
    float* out = (float*)d_out;

    float *agg_t, *agg_m, *bm0, *bm1, *bt0, *bt1, *inv_t, *inv_m, *Bext;
    int *e32_mt, *e32_tm;
    cudaGetSymbolAddress((void**)&agg_t, g_agg_t);
    cudaGetSymbolAddress((void**)&agg_m, g_agg_m);
    cudaGetSymbolAddress((void**)&bm0, g_bm0);
    cudaGetSymbolAddress((void**)&bm1, g_bm1);
    cudaGetSymbolAddress((void**)&bt0, g_bt0);
    cudaGetSymbolAddress((void**)&bt1, g_bt1);
    cudaGetSymbolAddress((void**)&inv_t, g_inv_t);
    cudaGetSymbolAddress((void**)&inv_m, g_inv_m);
    cudaGetSymbolAddress((void**)&Bext, g_Bext);
    cudaGetSymbolAddress((void**)&e32_mt, g_e32_mt);
    cudaGetSymbolAddress((void**)&e32_tm, g_e32_tm);

    const int scatterBlocks = CDIV(CDIV(NE, EPW) * 32, 256);
    const int aggT4 = NT * DD / 4;
    const int aggM4 = NM * DD / 4;

    // ---- preproc on the capture-origin (legacy) stream ----
    detect_reset<<<1, 1>>>();
    detect_kernel<<<256, 256>>>((const unsigned*)e_mt);
    convert_kernel<<<CDIV(2 * NE, 256), 256>>>(e_mt, e32_mt);
    convert_kernel<<<CDIV(2 * NE, 256), 256>>>(e_tm, e32_tm);
    prep_weights<<<CDIV(3 * 2 * K2 * DD, 256), 256>>>(Wl, Wr, Bext);

    // fork
    cudaEventRecord(evFork, 0);
    cudaStreamWaitEvent(sT, evFork, 0);
    cudaStreamWaitEvent(sM, evFork, 0);

    // per-stream one-time: zero agg+inv, degree counts, invert
    zero_two<<<2048, 256, 0, sT>>>((float4*)agg_t, aggT4, (float4*)inv_t, NT / 4);
    count_kernel<<<CDIV(NE, 256), 256, 0, sT>>>(e32_mt, (float*)inv_t);
    invert_kernel<<<CDIV(NT, 256), 256, 0, sT>>>((float*)inv_t, NT);

    zero_two<<<2048, 256, 0, sM>>>((float4*)agg_m, aggM4, (float4*)inv_m, NM / 4);
    count_kernel<<<CDIV(NE, 256), 256, 0, sM>>>(e32_tm, (float*)inv_m);
    invert_kernel<<<CDIV(NM, 256), 256, 0, sM>>>((float*)inv_m, NM);

    const float* xm_cur = x_m;   // input to scatter_t and gemm_m
    const float* xt_cur = x_t;   // input to scatter_m and gemm_t
    float* out_m = out;
    float* out_t = out + (size_t)NM * DD;

    for (int layer = 0; layer < 3; layer++) {
        float* xt_next = (layer == 2) ? out_t : ((layer == 0) ? bt0 : bt1);
        float* xm_next = (layer == 2) ? out_m : ((layer == 0) ? bm0 : bm1);
        int relu = (layer < 2) ? 1 : 0;

        // ---- track chain (stream T) ----
        if (layer > 0) {
            // agg_t last read by gemm_t(layer-1) — same stream, ordered.
            zero_kernel<<<2048, 256, 0, sT>>>((float4*)agg_t, aggT4);
            // xm_cur produced by gemm_m(layer-1) on stream M
            cudaStreamWaitEvent(sT, evGM[layer - 1], 0);
        }
        scatter_bulk<<<scatterBlocks, 256, 0, sT>>>(xm_cur, e32_mt, agg_t);
        gemm_sage_tc<<<CDIV(NT, 128), 256, 0, sT>>>(
            agg_t, (float*)inv_t, xt_cur,
            Bext + (size_t)(layer * 2 + 0) * K2 * DD,
            bl + (size_t)(layer * 2 + 0) * DD,
            xt_next, NT, relu);
        cudaEventRecord(evGT[layer], sT);

        // ---- musician chain (stream M) ----
        if (layer > 0) {
            zero_kernel<<<2048, 256, 0, sM>>>((float4*)agg_m, aggM4);
            cudaStreamWaitEvent(sM, evGT[layer - 1], 0);
        }
        scatter_bulk<<<scatterBlocks, 256, 0, sM>>>(xt_cur, e32_tm, agg_m);
        gemm_sage_tc<<<CDIV(NM, 128), 256, 0, sM>>>(
            agg_m, (float*)inv_m, xm_cur,
            Bext + (size_t)(layer * 2 + 1) * K2 * DD,
            bl + (size_t)(layer * 2 + 1) * DD,
            xm_next, NM, relu);
        cudaEventRecord(evGM[layer], sM);

        xm_cur = xm_next;
        xt_cur = xt_next;
    }

    // join back to the origin stream
    cudaStreamWaitEvent(0, evGT[2], 0);
    cudaStreamWaitEvent(0, evGM[2], 0);
}